// round 5
// baseline (speedup 1.0000x reference)
#include <cuda_runtime.h>

#define Bn 64
#define Dd 32
#define Hh 48
#define Ww 48
#define NA (Dd*Hh*Ww)        /* 73728 anchors per batch */
#define TOPK 60
#define NMS_TOPK 20
#define THRESH 0.15f
#define NMS_T 0.05f
#define NBINS 4096
#define NT 256
#define S_SLICES 18
#define SLOT 128
#define CAND_MAX (S_SLICES*SLOT)          /* 2304 */
#define FAST_MAX (2*NT)                   /* 512: fast-path candidate cap */
#define F4_PER_SLICE ((NA/4)/S_SLICES)    /* 1024 */
#define T_RAW 2.9f

__device__ unsigned long long g_scand[Bn][S_SLICES][SLOT];
__device__ int g_scnt[Bn][S_SLICES];
__device__ unsigned g_done[Bn];           /* never reset: old%18==17 marks last arrival */

__device__ __forceinline__ unsigned fkey(float f) {
    unsigned u = __float_as_uint(f);
    return u ^ ((u & 0x80000000u) ? 0xFFFFFFFFu : 0x80000000u);
}
__device__ __forceinline__ float finv(unsigned k) {
    unsigned u = (k & 0x80000000u) ? (k ^ 0x80000000u) : ~k;
    return __uint_as_float(u);
}
__device__ __forceinline__ void fence_gpu() {
    asm volatile("fence.acq_rel.gpu;" ::: "memory");
}

__global__ __launch_bounds__(NT)
void detfused(const float* __restrict__ Cls,
              const float* __restrict__ Shp,
              const float* __restrict__ Off,
              float* __restrict__ out)
{
    const int slice = blockIdx.x;
    const int b     = blockIdx.y;
    const int tid   = threadIdx.x;
    const int lane  = tid & 31;

    __shared__ int s_cnt;
    __shared__ unsigned long long s_stage[SLOT];
    __shared__ int s_sel;

    __shared__ union UU {
        unsigned hist[NBINS];                 /* 16 KB, fallback only */
        unsigned long long cand[CAND_MAX];    /* 18.4 KB */
    } u;
    __shared__ int partial[NT];
    __shared__ int s_off[S_SLICES];
    __shared__ int s_n[S_SLICES];
    __shared__ int s_bad;
    __shared__ int thr_bin;
    __shared__ int cand_cnt;
    __shared__ float s_score[TOPK];
    __shared__ float s_ctr[TOPK][3];
    __shared__ float s_ext[TOPK][3];
    __shared__ unsigned char s_valid[TOPK];
    __shared__ unsigned long long s_mask[TOPK];
    __shared__ unsigned long long s_keep;

    const float4* c4 = (const float4*)(Cls + (size_t)b * NA);

    // ================= phase 1: gated scan of this slice (MLP=4) =================
    if (tid == 0) s_cnt = 0;
    __syncthreads();

    {
        const int base = slice * F4_PER_SLICE + tid;
        float4 v0 = c4[base];
        float4 v1 = c4[base + NT];
        float4 v2 = c4[base + 2 * NT];
        float4 v3 = c4[base + 3 * NT];

        #pragma unroll
        for (int it = 0; it < 4; it++) {
            float4 v = (it == 0) ? v0 : (it == 1) ? v1 : (it == 2) ? v2 : v3;
            int gi = base + it * NT;
            #pragma unroll
            for (int k = 0; k < 4; k++) {
                float f = (k == 0) ? v.x : (k == 1) ? v.y : (k == 2) ? v.z : v.w;
                bool p = (f > T_RAW);
                unsigned ball = __ballot_sync(0xFFFFFFFFu, p);
                if (ball) {
                    int leader = __ffs(ball) - 1;
                    int pos = 0;
                    if (lane == leader) pos = atomicAdd(&s_cnt, __popc(ball));
                    pos = __shfl_sync(0xFFFFFFFFu, pos, leader);
                    if (p) {
                        int off = pos + __popc(ball & ((1u << lane) - 1u));
                        if (off < SLOT) {
                            unsigned idx = (unsigned)(gi * 4 + k);
                            s_stage[off] =
                                ((unsigned long long)fkey(f) << 32) | (unsigned)(~idx);
                        }
                    }
                }
            }
        }
    }
    __syncthreads();

    {
        int cnt = s_cnt;
        if (tid == 0) g_scnt[b][slice] = cnt;            // raw count (overflow detect)
        int w = min(cnt, SLOT);
        if (tid < w) g_scand[b][slice][tid] = s_stage[tid];
    }
    __syncthreads();                                     // all CTA stores issued

    // release (tid0 only) -> done counter; acquire (tid0 only) on selector side
    if (tid == 0) {
        fence_gpu();                                     // release our g_scand/g_scnt
        unsigned old = atomicAdd(&g_done[b], 1u);
        int sel = ((old % S_SLICES) == (S_SLICES - 1)) ? 1 : 0;
        s_sel = sel;
        if (sel) fence_gpu();                            // acquire others' writes
    }
    __syncthreads();
    if (!s_sel) return;

    // ================= phase 2 (last CTA of batch b): select + NMS =================
    if (tid == 0) {
        int acc = 0, bad = 0;
        #pragma unroll
        for (int s = 0; s < S_SLICES; s++) {
            int cs = g_scnt[b][s];
            if (cs > SLOT) bad = 1;
            int n = min(cs, SLOT);
            s_off[s] = acc;
            s_n[s]   = n;
            acc += n;
        }
        cand_cnt = acc;
        s_bad = bad | (acc < TOPK) | (acc > FAST_MAX);
    }
    __syncthreads();

    if (!s_bad) {
        // ---------- FAST PATH (c in [60, 512]) ----------
        // flat parallel gather: 9 independent predicated LDGs per thread
        #pragma unroll
        for (int i = tid; i < S_SLICES * SLOT; i += NT) {
            int s = i >> 7;          // /SLOT
            int j = i & (SLOT - 1);  // %SLOT
            if (j < s_n[s]) u.cand[s_off[s] + j] = g_scand[b][s][j];
        }
        __syncthreads();

        const int c = cand_cnt;
        bool act0 = (tid < c), act1 = (tid + NT < c);
        unsigned long long k0 = act0 ? u.cand[tid] : 0ull;
        unsigned long long k1 = act1 ? u.cand[tid + NT] : 0ull;

        // issue box loads NOW (registers), overlapping the rank loop below
        float az0=0, ay0=0, ax0=0, az1=0, ay1=0, ax1=0;
        float o00=0,o01=0,o02=0, h00=0,h01=0,h02=0;
        float o10=0,o11=0,o12=0, h10=0,h11=0,h12=0;
        if (act0) {
            unsigned idx = ~(unsigned)(k0 & 0xFFFFFFFFull);
            int z = (int)idx / (Hh * Ww);
            int rem = (int)idx % (Hh * Ww);
            az0 = (float)z; ay0 = (float)(rem / Ww); ax0 = (float)(rem % Ww);
            size_t base3 = (size_t)b * 3 * NA + idx;
            o00 = Off[base3]; o01 = Off[base3 + NA]; o02 = Off[base3 + 2 * NA];
            h00 = Shp[base3]; h01 = Shp[base3 + NA]; h02 = Shp[base3 + 2 * NA];
        }
        if (act1) {
            unsigned idx = ~(unsigned)(k1 & 0xFFFFFFFFull);
            int z = (int)idx / (Hh * Ww);
            int rem = (int)idx % (Hh * Ww);
            az1 = (float)z; ay1 = (float)(rem / Ww); ax1 = (float)(rem % Ww);
            size_t base3 = (size_t)b * 3 * NA + idx;
            o10 = Off[base3]; o11 = Off[base3 + NA]; o12 = Off[base3 + 2 * NA];
            h10 = Shp[base3]; h11 = Shp[base3 + NA]; h12 = Shp[base3 + 2 * NA];
        }

        // rank both slots in one sweep over shared
        int r0 = 0, r1 = 0;
        for (int j = 0; j < c; j++) {
            unsigned long long kj = u.cand[j];
            r0 += (kj > k0) ? 1 : 0;
            r1 += (kj > k1) ? 1 : 0;
        }

        if (act0 && r0 < TOPK) {
            float raw = finv((unsigned)(k0 >> 32));
            float sc  = 1.0f / (1.0f + __expf(-raw));
            s_score[r0] = sc;
            s_valid[r0] = (sc > THRESH) ? 1 : 0;
            s_ctr[r0][0] = (az0 + o00) * 2.0f;
            s_ctr[r0][1] = (ay0 + o01) * 2.0f;
            s_ctr[r0][2] = (ax0 + o02) * 2.0f;
            s_ext[r0][0] = 2.0f * h00;
            s_ext[r0][1] = 2.0f * h01;
            s_ext[r0][2] = 2.0f * h02;
        }
        if (act1 && r1 < TOPK) {
            float raw = finv((unsigned)(k1 >> 32));
            float sc  = 1.0f / (1.0f + __expf(-raw));
            s_score[r1] = sc;
            s_valid[r1] = (sc > THRESH) ? 1 : 0;
            s_ctr[r1][0] = (az1 + o10) * 2.0f;
            s_ctr[r1][1] = (ay1 + o11) * 2.0f;
            s_ctr[r1][2] = (ax1 + o12) * 2.0f;
            s_ext[r1][0] = 2.0f * h10;
            s_ext[r1][1] = 2.0f * h11;
            s_ext[r1][2] = 2.0f * h12;
        }
        __syncthreads();
    } else {
        // -------- exact histogram fallback (never hit on this data) --------
        for (int i = tid; i < NBINS; i += NT) u.hist[i] = 0u;
        if (tid == 0) { thr_bin = 0; cand_cnt = 0; }
        __syncthreads();
        for (int i = tid; i < NA / 4; i += NT) {
            float4 v = c4[i];
            #pragma unroll
            for (int k = 0; k < 4; k++) {
                float f = (k == 0) ? v.x : (k == 1) ? v.y : (k == 2) ? v.z : v.w;
                int bin = (int)(fkey(f) >> 20);
                unsigned m = __match_any_sync(0xFFFFFFFFu, bin);
                if (lane == (__ffs(m) - 1))
                    atomicAdd(&u.hist[bin], (unsigned)__popc(m));
            }
        }
        __syncthreads();
        const int BPT = NBINS / NT;                     // 16
        int hbase = tid * BPT;
        int loc = 0;
        #pragma unroll
        for (int j = 0; j < BPT; j++) loc += (int)u.hist[hbase + j];
        partial[tid] = loc;
        __syncthreads();
        if (tid == 0) {
            int run = 0;
            for (int t = NT - 1; t >= 0; t--) { int p = partial[t]; partial[t] = run; run += p; }
        }
        __syncthreads();
        {
            int cum_above = partial[tid];
            if (cum_above < TOPK && cum_above + loc >= TOPK) {
                int cum = cum_above;
                for (int j = BPT - 1; j >= 0; j--) {
                    cum += (int)u.hist[hbase + j];
                    if (cum >= TOPK) { thr_bin = hbase + j; break; }
                }
            }
        }
        __syncthreads();
        const unsigned klow = (unsigned)thr_bin << 20;
        __syncthreads();                                // done with hist before cand reuse
        for (int i = tid; i < NA / 4; i += NT) {
            float4 v = c4[i];
            #pragma unroll
            for (int k = 0; k < 4; k++) {
                float f = (k == 0) ? v.x : (k == 1) ? v.y : (k == 2) ? v.z : v.w;
                unsigned key = fkey(f);
                if (key >= klow) {
                    int pos = atomicAdd(&cand_cnt, 1);
                    if (pos < CAND_MAX) {
                        unsigned idx = (unsigned)(i * 4 + k);
                        u.cand[pos] = ((unsigned long long)key << 32) | (unsigned)(~idx);
                    }
                }
            }
        }
        __syncthreads();

        // generic rank-then-gather (c up to CAND_MAX)
        const int c = min(cand_cnt, CAND_MAX);
        for (int i = tid; i < c; i += NT) {
            unsigned long long ki = u.cand[i];
            int rank = 0;
            for (int j = 0; j < c; j++) rank += (u.cand[j] > ki) ? 1 : 0;
            if (rank < TOPK) {
                unsigned key = (unsigned)(ki >> 32);
                unsigned idx = ~(unsigned)(ki & 0xFFFFFFFFull);
                float raw = finv(key);
                float sc  = 1.0f / (1.0f + expf(-raw));
                s_score[rank] = sc;
                s_valid[rank] = (sc > THRESH) ? 1 : 0;
                int z   = (int)idx / (Hh * Ww);
                int rem = (int)idx % (Hh * Ww);
                int y   = rem / Ww;
                int x   = rem % Ww;
                size_t base3 = (size_t)b * 3 * NA + idx;
                float o0 = Off[base3], o1 = Off[base3 + NA], o2 = Off[base3 + 2 * NA];
                float h0 = Shp[base3], h1 = Shp[base3 + NA], h2 = Shp[base3 + 2 * NA];
                s_ctr[rank][0] = ((float)z + o0) * 2.0f;
                s_ctr[rank][1] = ((float)y + o1) * 2.0f;
                s_ctr[rank][2] = ((float)x + o2) * 2.0f;
                s_ext[rank][0] = 2.0f * h0;
                s_ext[rank][1] = 2.0f * h1;
                s_ext[rank][2] = 2.0f * h2;
            }
        }
        __syncthreads();
    }

    // ---- IoU > NMS_T bitmask, one row per thread ----
    if (tid < TOPK) {
        float ci0 = s_ctr[tid][0], ci1 = s_ctr[tid][1], ci2 = s_ctr[tid][2];
        float ei0 = s_ext[tid][0], ei1 = s_ext[tid][1], ei2 = s_ext[tid][2];
        float li0 = ci0 - 0.5f * ei0, li1 = ci1 - 0.5f * ei1, li2 = ci2 - 0.5f * ei2;
        float hi0 = ci0 + 0.5f * ei0, hi1 = ci1 + 0.5f * ei1, hi2 = ci2 + 0.5f * ei2;
        float vi  = ei0 * ei1 * ei2;
        unsigned long long m = 0ull;
        #pragma unroll 4
        for (int j = 0; j < TOPK; j++) {
            float ej0 = s_ext[j][0], ej1 = s_ext[j][1], ej2 = s_ext[j][2];
            float lj0 = s_ctr[j][0] - 0.5f * ej0;
            float lj1 = s_ctr[j][1] - 0.5f * ej1;
            float lj2 = s_ctr[j][2] - 0.5f * ej2;
            float hj0 = s_ctr[j][0] + 0.5f * ej0;
            float hj1 = s_ctr[j][1] + 0.5f * ej1;
            float hj2 = s_ctr[j][2] + 0.5f * ej2;
            float d0 = fminf(hi0, hj0) - fmaxf(li0, lj0);
            float d1 = fminf(hi1, hj1) - fmaxf(li1, lj1);
            float d2 = fminf(hi2, hj2) - fmaxf(li2, lj2);
            float inter = fmaxf(d0, 0.0f) * fmaxf(d1, 0.0f) * fmaxf(d2, 0.0f);
            float vj  = ej0 * ej1 * ej2;
            float un  = vi + vj - inter;
            float iou = inter / fmaxf(un, 1e-8f);
            if (iou > NMS_T) m |= (1ull << j);
        }
        s_mask[tid] = m;
    }
    __syncthreads();

    // ---- greedy NMS on a u64 mask ----
    if (tid == 0) {
        unsigned long long km = 0ull;
        #pragma unroll 4
        for (int i = 0; i < TOPK; i++)
            if (s_valid[i] && !(s_mask[i] & km)) km |= (1ull << i);
        s_keep = km;
    }
    __syncthreads();

    // ---- write output: fill -1, then kept rows at their rank ----
    float* ob = out + (size_t)b * TOPK * 8;
    for (int i = tid; i < TOPK * 8; i += NT) ob[i] = -1.0f;
    __syncthreads();
    if (tid < TOPK) {
        unsigned long long km = s_keep;
        if ((km >> tid) & 1ull) {
            int rank = __popcll(km & ((1ull << tid) - 1ull));
            if (rank < NMS_TOPK) {
                float* row = ob + (size_t)rank * 8;
                row[0] = 1.0f;
                row[1] = s_score[tid];
                row[2] = s_ctr[tid][0];
                row[3] = s_ctr[tid][1];
                row[4] = s_ctr[tid][2];
                row[5] = s_ext[tid][0];
                row[6] = s_ext[tid][1];
                row[7] = s_ext[tid][2];
            }
        }
    }
}

extern "C" void kernel_launch(void* const* d_in, const int* in_sizes, int n_in,
                              void* d_out, int out_size)
{
    const float* Cls = (const float*)d_in[0];
    const float* Shp = (const float*)d_in[1];
    const float* Off = (const float*)d_in[2];
    float* out = (float*)d_out;

    dim3 grid(S_SLICES, Bn);
    detfused<<<grid, NT>>>(Cls, Shp, Off, out);
}

// round 6
// speedup vs baseline: 1.2737x; 1.2737x over previous
#include <cuda_runtime.h>

#define Bn 64
#define Dd 32
#define Hh 48
#define Ww 48
#define NA (Dd*Hh*Ww)        /* 73728 anchors per batch */
#define TOPK 60
#define NMS_TOPK 20
#define THRESH 0.15f
#define NMS_T 0.05f
#define NBINS 4096
#define NT 256
#define S_SLICES 9
#define SLOT 64
#define NSLOTS (S_SLICES*SLOT)            /* 576 */
#define CAND_FB 2304                      /* fallback capacity */
#define F4_PER_SLICE ((NA/4)/S_SLICES)    /* 2048 */
#define F4_PER_THREAD (F4_PER_SLICE/NT)   /* 8 */
#define T_RAW 2.9f

__device__ unsigned long long g_scand[Bn][S_SLICES][SLOT];
__device__ int g_scnt[Bn][S_SLICES];
__device__ unsigned g_done[Bn];           /* never reset: old%9==8 marks last arrival */

__device__ __forceinline__ unsigned fkey(float f) {
    unsigned u = __float_as_uint(f);
    return u ^ ((u & 0x80000000u) ? 0xFFFFFFFFu : 0x80000000u);
}
__device__ __forceinline__ float finv(unsigned k) {
    unsigned u = (k & 0x80000000u) ? (k ^ 0x80000000u) : ~k;
    return __uint_as_float(u);
}
__device__ __forceinline__ void fence_gpu() {
    asm volatile("fence.acq_rel.gpu;" ::: "memory");
}

__global__ __launch_bounds__(NT)
void detfused(const float* __restrict__ Cls,
              const float* __restrict__ Shp,
              const float* __restrict__ Off,
              float* __restrict__ out)
{
    const int slice = blockIdx.x;
    const int b     = blockIdx.y;
    const int tid   = threadIdx.x;

    __shared__ int s_cnt;
    __shared__ unsigned long long s_stage[SLOT];
    __shared__ int s_sel;

    __shared__ union UU {
        unsigned hist[NBINS];                 /* 16 KB, fallback only */
        unsigned long long cand[CAND_FB];     /* 18.4 KB */
    } u;
    __shared__ int partial[NT];
    __shared__ int s_off[S_SLICES];
    __shared__ int s_n[S_SLICES];
    __shared__ int s_bad;
    __shared__ int thr_bin;
    __shared__ int cand_cnt;
    __shared__ float s_score[TOPK];
    __shared__ float s_ctr[TOPK][3];
    __shared__ float s_ext[TOPK][3];
    __shared__ unsigned char s_valid[TOPK];
    __shared__ unsigned long long s_mask[TOPK];
    __shared__ unsigned long long s_keep;

    const float4* c4 = (const float4*)(Cls + (size_t)b * NA);

    // ================= phase 1: sparse gated scan (MLP=8, no ballots) ============
    if (tid == 0) s_cnt = 0;
    __syncthreads();

    {
        const int base = slice * F4_PER_SLICE + tid;
        float4 v[F4_PER_THREAD];
        #pragma unroll
        for (int it = 0; it < F4_PER_THREAD; it++) v[it] = c4[base + it * NT];

        #pragma unroll
        for (int it = 0; it < F4_PER_THREAD; it++) {
            float4 q = v[it];
            float mx = fmaxf(fmaxf(q.x, q.y), fmaxf(q.z, q.w));
            if (mx > T_RAW) {                          // rare (~p=0.0075/thread-f4)
                int gi = base + it * NT;
                #pragma unroll
                for (int k = 0; k < 4; k++) {
                    float f = (k == 0) ? q.x : (k == 1) ? q.y : (k == 2) ? q.z : q.w;
                    if (f > T_RAW) {
                        int off = atomicAdd(&s_cnt, 1);
                        if (off < SLOT) {
                            unsigned idx = (unsigned)(gi * 4 + k);
                            s_stage[off] =
                                ((unsigned long long)fkey(f) << 32) | (unsigned)(~idx);
                        }
                    }
                }
            }
        }
    }
    __syncthreads();

    {
        int cnt = s_cnt;
        if (tid == 0) g_scnt[b][slice] = cnt;            // raw count (overflow detect)
        int w = min(cnt, SLOT);
        if (tid < w) g_scand[b][slice][tid] = s_stage[tid];
    }
    __syncthreads();                                     // all CTA stores issued

    if (tid == 0) {
        fence_gpu();                                     // release g_scand/g_scnt
        unsigned old = atomicAdd(&g_done[b], 1u);
        int sel = ((old % S_SLICES) == (S_SLICES - 1)) ? 1 : 0;
        s_sel = sel;
        if (sel) fence_gpu();                            // acquire peers' writes
    }
    __syncthreads();
    if (!s_sel) return;

    // ================= phase 2 (last CTA of batch b): select + NMS ================
    if (tid == 0) {
        int acc = 0, bad = 0;
        #pragma unroll
        for (int s = 0; s < S_SLICES; s++) {
            int cs = g_scnt[b][s];
            if (cs > SLOT) bad = 1;
            int n = min(cs, SLOT);
            s_off[s] = acc;
            s_n[s]   = n;
            acc += n;
        }
        cand_cnt = acc;
        s_bad = bad | (acc < TOPK) | (acc > NT);
    }
    __syncthreads();

    if (!s_bad) {
        // ---------- FAST PATH (c in [60, 256]) ----------
        #pragma unroll
        for (int i = tid; i < NSLOTS; i += NT) {         // 576 slots / 256 thr
            int s = i >> 6;           // /SLOT
            int j = i & (SLOT - 1);   // %SLOT
            if (j < s_n[s]) u.cand[s_off[s] + j] = g_scand[b][s][j];
        }
        __syncthreads();

        const int c = cand_cnt;
        bool act = (tid < c);
        unsigned long long k0 = act ? u.cand[tid] : 0ull;

        // issue scattered box loads NOW; they overlap the rank loop below
        float az = 0, ay = 0, ax = 0;
        float o0 = 0, o1 = 0, o2 = 0, h0 = 0, h1 = 0, h2 = 0;
        if (act) {
            unsigned idx = ~(unsigned)(k0 & 0xFFFFFFFFull);
            int z = (int)idx / (Hh * Ww);
            int rem = (int)idx % (Hh * Ww);
            az = (float)z; ay = (float)(rem / Ww); ax = (float)(rem % Ww);
            size_t base3 = (size_t)b * 3 * NA + idx;
            o0 = Off[base3]; o1 = Off[base3 + NA]; o2 = Off[base3 + 2 * NA];
            h0 = Shp[base3]; h1 = Shp[base3 + NA]; h2 = Shp[base3 + 2 * NA];
        }

        int r0 = 0;
        for (int j = 0; j < c; j++)                      // broadcast LDS
            r0 += (u.cand[j] > k0) ? 1 : 0;

        if (act && r0 < TOPK) {
            float raw = finv((unsigned)(k0 >> 32));
            float sc  = 1.0f / (1.0f + __expf(-raw));
            s_score[r0] = sc;
            s_valid[r0] = (sc > THRESH) ? 1 : 0;
            s_ctr[r0][0] = (az + o0) * 2.0f;             // stride = (2,2,2)
            s_ctr[r0][1] = (ay + o1) * 2.0f;
            s_ctr[r0][2] = (ax + o2) * 2.0f;
            s_ext[r0][0] = 2.0f * h0;
            s_ext[r0][1] = 2.0f * h1;
            s_ext[r0][2] = 2.0f * h2;
        }
        __syncthreads();
    } else {
        // -------- exact histogram fallback (never hit on this data) --------
        const int lane = tid & 31;
        for (int i = tid; i < NBINS; i += NT) u.hist[i] = 0u;
        if (tid == 0) { thr_bin = 0; cand_cnt = 0; }
        __syncthreads();
        for (int i = tid; i < NA / 4; i += NT) {
            float4 v = c4[i];
            #pragma unroll
            for (int k = 0; k < 4; k++) {
                float f = (k == 0) ? v.x : (k == 1) ? v.y : (k == 2) ? v.z : v.w;
                int bin = (int)(fkey(f) >> 20);
                unsigned m = __match_any_sync(0xFFFFFFFFu, bin);
                if (lane == (__ffs(m) - 1))
                    atomicAdd(&u.hist[bin], (unsigned)__popc(m));
            }
        }
        __syncthreads();
        const int BPT = NBINS / NT;                      // 16
        int hbase = tid * BPT;
        int loc = 0;
        #pragma unroll
        for (int j = 0; j < BPT; j++) loc += (int)u.hist[hbase + j];
        partial[tid] = loc;
        __syncthreads();
        if (tid == 0) {
            int run = 0;
            for (int t = NT - 1; t >= 0; t--) { int p = partial[t]; partial[t] = run; run += p; }
        }
        __syncthreads();
        {
            int cum_above = partial[tid];
            if (cum_above < TOPK && cum_above + loc >= TOPK) {
                int cum = cum_above;
                for (int j = BPT - 1; j >= 0; j--) {
                    cum += (int)u.hist[hbase + j];
                    if (cum >= TOPK) { thr_bin = hbase + j; break; }
                }
            }
        }
        __syncthreads();
        const unsigned klow = (unsigned)thr_bin << 20;
        __syncthreads();                                 // done with hist before reuse
        for (int i = tid; i < NA / 4; i += NT) {
            float4 v = c4[i];
            #pragma unroll
            for (int k = 0; k < 4; k++) {
                float f = (k == 0) ? v.x : (k == 1) ? v.y : (k == 2) ? v.z : v.w;
                unsigned key = fkey(f);
                if (key >= klow) {
                    int pos = atomicAdd(&cand_cnt, 1);
                    if (pos < CAND_FB) {
                        unsigned idx = (unsigned)(i * 4 + k);
                        u.cand[pos] = ((unsigned long long)key << 32) | (unsigned)(~idx);
                    }
                }
            }
        }
        __syncthreads();

        const int c = min(cand_cnt, CAND_FB);
        for (int i = tid; i < c; i += NT) {
            unsigned long long ki = u.cand[i];
            int rank = 0;
            for (int j = 0; j < c; j++) rank += (u.cand[j] > ki) ? 1 : 0;
            if (rank < TOPK) {
                unsigned key = (unsigned)(ki >> 32);
                unsigned idx = ~(unsigned)(ki & 0xFFFFFFFFull);
                float raw = finv(key);
                float sc  = 1.0f / (1.0f + expf(-raw));
                s_score[rank] = sc;
                s_valid[rank] = (sc > THRESH) ? 1 : 0;
                int z   = (int)idx / (Hh * Ww);
                int rem = (int)idx % (Hh * Ww);
                int y   = rem / Ww;
                int x   = rem % Ww;
                size_t base3 = (size_t)b * 3 * NA + idx;
                float o0 = Off[base3], o1 = Off[base3 + NA], o2 = Off[base3 + 2 * NA];
                float h0 = Shp[base3], h1 = Shp[base3 + NA], h2 = Shp[base3 + 2 * NA];
                s_ctr[rank][0] = ((float)z + o0) * 2.0f;
                s_ctr[rank][1] = ((float)y + o1) * 2.0f;
                s_ctr[rank][2] = ((float)x + o2) * 2.0f;
                s_ext[rank][0] = 2.0f * h0;
                s_ext[rank][1] = 2.0f * h1;
                s_ext[rank][2] = 2.0f * h2;
            }
        }
        __syncthreads();
    }

    // ---- IoU > NMS_T bitmask, one row per thread ----
    if (tid < TOPK) {
        float ci0 = s_ctr[tid][0], ci1 = s_ctr[tid][1], ci2 = s_ctr[tid][2];
        float ei0 = s_ext[tid][0], ei1 = s_ext[tid][1], ei2 = s_ext[tid][2];
        float li0 = ci0 - 0.5f * ei0, li1 = ci1 - 0.5f * ei1, li2 = ci2 - 0.5f * ei2;
        float hi0 = ci0 + 0.5f * ei0, hi1 = ci1 + 0.5f * ei1, hi2 = ci2 + 0.5f * ei2;
        float vi  = ei0 * ei1 * ei2;
        unsigned long long m = 0ull;
        #pragma unroll 4
        for (int j = 0; j < TOPK; j++) {
            float ej0 = s_ext[j][0], ej1 = s_ext[j][1], ej2 = s_ext[j][2];
            float lj0 = s_ctr[j][0] - 0.5f * ej0;
            float lj1 = s_ctr[j][1] - 0.5f * ej1;
            float lj2 = s_ctr[j][2] - 0.5f * ej2;
            float hj0 = s_ctr[j][0] + 0.5f * ej0;
            float hj1 = s_ctr[j][1] + 0.5f * ej1;
            float hj2 = s_ctr[j][2] + 0.5f * ej2;
            float d0 = fminf(hi0, hj0) - fmaxf(li0, lj0);
            float d1 = fminf(hi1, hj1) - fmaxf(li1, lj1);
            float d2 = fminf(hi2, hj2) - fmaxf(li2, lj2);
            float inter = fmaxf(d0, 0.0f) * fmaxf(d1, 0.0f) * fmaxf(d2, 0.0f);
            float vj  = ej0 * ej1 * ej2;
            float un  = vi + vj - inter;
            float iou = inter / fmaxf(un, 1e-8f);
            if (iou > NMS_T) m |= (1ull << j);
        }
        s_mask[tid] = m;
    }
    __syncthreads();

    // ---- greedy NMS on a u64 mask ----
    if (tid == 0) {
        unsigned long long km = 0ull;
        #pragma unroll 4
        for (int i = 0; i < TOPK; i++)
            if (s_valid[i] && !(s_mask[i] & km)) km |= (1ull << i);
        s_keep = km;
    }
    __syncthreads();

    // ---- write output: fill -1, then kept rows at their rank ----
    float* ob = out + (size_t)b * TOPK * 8;
    for (int i = tid; i < TOPK * 8; i += NT) ob[i] = -1.0f;
    __syncthreads();
    if (tid < TOPK) {
        unsigned long long km = s_keep;
        if ((km >> tid) & 1ull) {
            int rank = __popcll(km & ((1ull << tid) - 1ull));
            if (rank < NMS_TOPK) {
                float* row = ob + (size_t)rank * 8;
                row[0] = 1.0f;
                row[1] = s_score[tid];
                row[2] = s_ctr[tid][0];
                row[3] = s_ctr[tid][1];
                row[4] = s_ctr[tid][2];
                row[5] = s_ext[tid][0];
                row[6] = s_ext[tid][1];
                row[7] = s_ext[tid][2];
            }
        }
    }
}

extern "C" void kernel_launch(void* const* d_in, const int* in_sizes, int n_in,
                              void* d_out, int out_size)
{
    const float* Cls = (const float*)d_in[0];
    const float* Shp = (const float*)d_in[1];
    const float* Off = (const float*)d_in[2];
    float* out = (float*)d_out;

    dim3 grid(S_SLICES, Bn);
    detfused<<<grid, NT>>>(Cls, Shp, Off, out);
}

// round 7
// speedup vs baseline: 1.6626x; 1.3053x over previous
#include <cuda_runtime.h>

#define Bn 64
#define Dd 32
#define Hh 48
#define Ww 48
#define NA (Dd*Hh*Ww)        /* 73728 anchors per batch */
#define TOPK 60
#define NMS_TOPK 20
#define THRESH 0.15f
#define NMS_T 0.05f
#define NBINS 4096
#define NT 256
#define S_SLICES 9
#define SLOT 64
#define NSLOTS (S_SLICES*SLOT)            /* 576 */
#define CAND_FB 2304                      /* fallback capacity */
#define F4_PER_SLICE ((NA/4)/S_SLICES)    /* 2048 */
#define F4_PER_THREAD (F4_PER_SLICE/NT)   /* 8 */
#define T_RAW 2.9f

__device__ unsigned long long g_scand[Bn][S_SLICES][SLOT];
__device__ int g_scnt[Bn][S_SLICES];
__device__ unsigned g_done[Bn];           /* never reset: old%9==8 marks last arrival */

__device__ __forceinline__ unsigned fkey(float f) {
    unsigned u = __float_as_uint(f);
    return u ^ ((u & 0x80000000u) ? 0xFFFFFFFFu : 0x80000000u);
}
__device__ __forceinline__ float finv(unsigned k) {
    unsigned u = (k & 0x80000000u) ? (k ^ 0x80000000u) : ~k;
    return __uint_as_float(u);
}
__device__ __forceinline__ void fence_gpu() {
    asm volatile("fence.acq_rel.gpu;" ::: "memory");
}

__global__ __launch_bounds__(NT)
void detfused(const float* __restrict__ Cls,
              const float* __restrict__ Shp,
              const float* __restrict__ Off,
              float* __restrict__ out)
{
    const int slice = blockIdx.x;
    const int b     = blockIdx.y;
    const int tid   = threadIdx.x;

    __shared__ int s_cnt;
    __shared__ unsigned long long s_stage[SLOT];
    __shared__ int s_sel;

    __shared__ union UU {
        unsigned hist[NBINS];                 /* 16 KB, fallback only */
        unsigned long long cand[CAND_FB];     /* 18.4 KB */
    } u;
    __shared__ int partial[NT];
    __shared__ int s_off[S_SLICES];
    __shared__ int s_n[S_SLICES];
    __shared__ int s_bad;
    __shared__ int thr_bin;
    __shared__ int cand_cnt;
    __shared__ float s_score[TOPK];
    __shared__ float s_ctr[TOPK][3];
    __shared__ float s_ext[TOPK][3];
    __shared__ unsigned char s_valid[TOPK];
    __shared__ unsigned long long s_mask[TOPK];
    __shared__ unsigned long long s_keep;

    const float4* c4 = (const float4*)(Cls + (size_t)b * NA);
    float* ob = out + (size_t)b * TOPK * 8;

    // ================= phase 1: sparse gated scan (1 branch/thread) ===============
    if (tid == 0) s_cnt = 0;
    __syncthreads();

    {
        const int base = slice * F4_PER_SLICE + tid;
        float4 v[F4_PER_THREAD];
        #pragma unroll
        for (int it = 0; it < F4_PER_THREAD; it++) v[it] = c4[base + it * NT];

        // branchless per-group hit mask
        unsigned hm = 0;
        #pragma unroll
        for (int it = 0; it < F4_PER_THREAD; it++) {
            float4 q = v[it];
            float mx = fmaxf(fmaxf(q.x, q.y), fmaxf(q.z, q.w));
            hm |= (mx > T_RAW) ? (1u << it) : 0u;
        }

        if (hm) {                                        // ~5.8% of threads
            #pragma unroll
            for (int it = 0; it < F4_PER_THREAD; it++) {
                if (hm & (1u << it)) {
                    float4 q = v[it];
                    int gi = base + it * NT;
                    #pragma unroll
                    for (int k = 0; k < 4; k++) {
                        float f = (k == 0) ? q.x : (k == 1) ? q.y : (k == 2) ? q.z : q.w;
                        if (f > T_RAW) {
                            int off = atomicAdd(&s_cnt, 1);
                            if (off < SLOT) {
                                unsigned idx = (unsigned)(gi * 4 + k);
                                s_stage[off] =
                                    ((unsigned long long)fkey(f) << 32) | (unsigned)(~idx);
                            }
                        }
                    }
                }
            }
        }
    }

    // slice-0 CTA prefills this batch's output with -1 (off the selector's path)
    if (slice == 0) {
        for (int i = tid; i < TOPK * 8; i += NT) ob[i] = -1.0f;
    }
    __syncthreads();

    {
        int cnt = s_cnt;
        if (tid == 0) g_scnt[b][slice] = cnt;            // raw count (overflow detect)
        int w = min(cnt, SLOT);
        if (tid < w) g_scand[b][slice][tid] = s_stage[tid];
    }
    __syncthreads();                                     // all CTA stores issued

    if (tid == 0) {
        fence_gpu();                                     // release g_scand/g_scnt/fill
        unsigned old = atomicAdd(&g_done[b], 1u);
        int sel = ((old % S_SLICES) == (S_SLICES - 1)) ? 1 : 0;
        s_sel = sel;
        if (sel) fence_gpu();                            // acquire peers' writes
    }
    __syncthreads();
    if (!s_sel) return;

    // ================= phase 2 (last CTA of batch b): select + NMS ================
    if (tid == 0) {
        int acc = 0, bad = 0;
        #pragma unroll
        for (int s = 0; s < S_SLICES; s++) {
            int cs = g_scnt[b][s];
            if (cs > SLOT) bad = 1;
            int n = min(cs, SLOT);
            s_off[s] = acc;
            s_n[s]   = n;
            acc += n;
        }
        cand_cnt = acc;
        s_bad = bad | (acc < TOPK) | (acc > NT);
    }
    if (tid < TOPK) s_mask[tid] = 0ull;                  // for atomicOr IoU
    __syncthreads();

    if (!s_bad) {
        // ---------- FAST PATH (c in [60, 256]) ----------
        #pragma unroll
        for (int i = tid; i < NSLOTS; i += NT) {         // 576 slots / 256 thr
            int s = i >> 6;           // /SLOT
            int j = i & (SLOT - 1);   // %SLOT
            if (j < s_n[s]) u.cand[s_off[s] + j] = g_scand[b][s][j];
        }
        __syncthreads();

        const int c = cand_cnt;
        bool act = (tid < c);
        unsigned long long k0 = act ? u.cand[tid] : 0ull;

        // issue scattered box loads NOW; they overlap the rank loop below
        float az = 0, ay = 0, ax = 0;
        float o0 = 0, o1 = 0, o2 = 0, h0 = 0, h1 = 0, h2 = 0;
        if (act) {
            unsigned idx = ~(unsigned)(k0 & 0xFFFFFFFFull);
            int z = (int)idx / (Hh * Ww);
            int rem = (int)idx % (Hh * Ww);
            az = (float)z; ay = (float)(rem / Ww); ax = (float)(rem % Ww);
            size_t base3 = (size_t)b * 3 * NA + idx;
            o0 = Off[base3]; o1 = Off[base3 + NA]; o2 = Off[base3 + 2 * NA];
            h0 = Shp[base3]; h1 = Shp[base3 + NA]; h2 = Shp[base3 + 2 * NA];
        }

        int r0 = 0;
        for (int j = 0; j < c; j++)                      // broadcast LDS
            r0 += (u.cand[j] > k0) ? 1 : 0;

        if (act && r0 < TOPK) {
            float raw = finv((unsigned)(k0 >> 32));
            float sc  = 1.0f / (1.0f + __expf(-raw));
            s_score[r0] = sc;
            s_valid[r0] = (sc > THRESH) ? 1 : 0;
            s_ctr[r0][0] = (az + o0) * 2.0f;             // stride = (2,2,2)
            s_ctr[r0][1] = (ay + o1) * 2.0f;
            s_ctr[r0][2] = (ax + o2) * 2.0f;
            s_ext[r0][0] = 2.0f * h0;
            s_ext[r0][1] = 2.0f * h1;
            s_ext[r0][2] = 2.0f * h2;
        }
        __syncthreads();
    } else {
        // -------- exact histogram fallback (never hit on this data) --------
        const int lane = tid & 31;
        for (int i = tid; i < NBINS; i += NT) u.hist[i] = 0u;
        if (tid == 0) { thr_bin = 0; cand_cnt = 0; }
        __syncthreads();
        for (int i = tid; i < NA / 4; i += NT) {
            float4 v = c4[i];
            #pragma unroll
            for (int k = 0; k < 4; k++) {
                float f = (k == 0) ? v.x : (k == 1) ? v.y : (k == 2) ? v.z : v.w;
                int bin = (int)(fkey(f) >> 20);
                unsigned m = __match_any_sync(0xFFFFFFFFu, bin);
                if (lane == (__ffs(m) - 1))
                    atomicAdd(&u.hist[bin], (unsigned)__popc(m));
            }
        }
        __syncthreads();
        const int BPT = NBINS / NT;                      // 16
        int hbase = tid * BPT;
        int loc = 0;
        #pragma unroll
        for (int j = 0; j < BPT; j++) loc += (int)u.hist[hbase + j];
        partial[tid] = loc;
        __syncthreads();
        if (tid == 0) {
            int run = 0;
            for (int t = NT - 1; t >= 0; t--) { int p = partial[t]; partial[t] = run; run += p; }
        }
        __syncthreads();
        {
            int cum_above = partial[tid];
            if (cum_above < TOPK && cum_above + loc >= TOPK) {
                int cum = cum_above;
                for (int j = BPT - 1; j >= 0; j--) {
                    cum += (int)u.hist[hbase + j];
                    if (cum >= TOPK) { thr_bin = hbase + j; break; }
                }
            }
        }
        __syncthreads();
        const unsigned klow = (unsigned)thr_bin << 20;
        __syncthreads();                                 // done with hist before reuse
        for (int i = tid; i < NA / 4; i += NT) {
            float4 v = c4[i];
            #pragma unroll
            for (int k = 0; k < 4; k++) {
                float f = (k == 0) ? v.x : (k == 1) ? v.y : (k == 2) ? v.z : v.w;
                unsigned key = fkey(f);
                if (key >= klow) {
                    int pos = atomicAdd(&cand_cnt, 1);
                    if (pos < CAND_FB) {
                        unsigned idx = (unsigned)(i * 4 + k);
                        u.cand[pos] = ((unsigned long long)key << 32) | (unsigned)(~idx);
                    }
                }
            }
        }
        __syncthreads();

        const int c = min(cand_cnt, CAND_FB);
        for (int i = tid; i < c; i += NT) {
            unsigned long long ki = u.cand[i];
            int rank = 0;
            for (int j = 0; j < c; j++) rank += (u.cand[j] > ki) ? 1 : 0;
            if (rank < TOPK) {
                unsigned key = (unsigned)(ki >> 32);
                unsigned idx = ~(unsigned)(ki & 0xFFFFFFFFull);
                float raw = finv(key);
                float sc  = 1.0f / (1.0f + expf(-raw));
                s_score[rank] = sc;
                s_valid[rank] = (sc > THRESH) ? 1 : 0;
                int z   = (int)idx / (Hh * Ww);
                int rem = (int)idx % (Hh * Ww);
                int y   = rem / Ww;
                int x   = rem % Ww;
                size_t base3 = (size_t)b * 3 * NA + idx;
                float o0 = Off[base3], o1 = Off[base3 + NA], o2 = Off[base3 + 2 * NA];
                float h0 = Shp[base3], h1 = Shp[base3 + NA], h2 = Shp[base3 + 2 * NA];
                s_ctr[rank][0] = ((float)z + o0) * 2.0f;
                s_ctr[rank][1] = ((float)y + o1) * 2.0f;
                s_ctr[rank][2] = ((float)x + o2) * 2.0f;
                s_ext[rank][0] = 2.0f * h0;
                s_ext[rank][1] = 2.0f * h1;
                s_ext[rank][2] = 2.0f * h2;
            }
        }
        __syncthreads();

        // fallback must also (re)fill output since fast fill happened pre-selection
        for (int i = tid; i < TOPK * 8; i += NT) ob[i] = -1.0f;
        __syncthreads();
    }

    // ---- IoU > NMS_T bitmask: 240 threads, 15-col strips ----
    {
        int i = tid % TOPK;           // row
        int q = tid / TOPK;           // strip 0..3 (tid<240)
        if (q < 4) {
            float ci0 = s_ctr[i][0], ci1 = s_ctr[i][1], ci2 = s_ctr[i][2];
            float ei0 = s_ext[i][0], ei1 = s_ext[i][1], ei2 = s_ext[i][2];
            float li0 = ci0 - 0.5f * ei0, li1 = ci1 - 0.5f * ei1, li2 = ci2 - 0.5f * ei2;
            float hi0 = ci0 + 0.5f * ei0, hi1 = ci1 + 0.5f * ei1, hi2 = ci2 + 0.5f * ei2;
            float vi  = ei0 * ei1 * ei2;
            unsigned long long m = 0ull;
            int j0 = q * 15;
            #pragma unroll
            for (int t = 0; t < 15; t++) {
                int j = j0 + t;
                float ej0 = s_ext[j][0], ej1 = s_ext[j][1], ej2 = s_ext[j][2];
                float lj0 = s_ctr[j][0] - 0.5f * ej0;
                float lj1 = s_ctr[j][1] - 0.5f * ej1;
                float lj2 = s_ctr[j][2] - 0.5f * ej2;
                float hj0 = s_ctr[j][0] + 0.5f * ej0;
                float hj1 = s_ctr[j][1] + 0.5f * ej1;
                float hj2 = s_ctr[j][2] + 0.5f * ej2;
                float d0 = fminf(hi0, hj0) - fmaxf(li0, lj0);
                float d1 = fminf(hi1, hj1) - fmaxf(li1, lj1);
                float d2 = fminf(hi2, hj2) - fmaxf(li2, lj2);
                float inter = fmaxf(d0, 0.0f) * fmaxf(d1, 0.0f) * fmaxf(d2, 0.0f);
                float vj  = ej0 * ej1 * ej2;
                float un  = vi + vj - inter;
                float iou = inter / fmaxf(un, 1e-8f);
                if (iou > NMS_T) m |= (1ull << j);
            }
            if (m) atomicOr(&s_mask[i], m);
        }
    }
    __syncthreads();

    // ---- greedy NMS on a u64 mask ----
    if (tid == 0) {
        unsigned long long km = 0ull;
        #pragma unroll 4
        for (int i = 0; i < TOPK; i++)
            if (s_valid[i] && !(s_mask[i] & km)) km |= (1ull << i);
        s_keep = km;
    }
    __syncthreads();

    // ---- write kept rows at their rank (output already -1-filled) ----
    if (tid < TOPK) {
        unsigned long long km = s_keep;
        if ((km >> tid) & 1ull) {
            int rank = __popcll(km & ((1ull << tid) - 1ull));
            if (rank < NMS_TOPK) {
                float* row = ob + (size_t)rank * 8;
                row[0] = 1.0f;
                row[1] = s_score[tid];
                row[2] = s_ctr[tid][0];
                row[3] = s_ctr[tid][1];
                row[4] = s_ctr[tid][2];
                row[5] = s_ext[tid][0];
                row[6] = s_ext[tid][1];
                row[7] = s_ext[tid][2];
            }
        }
    }
}

extern "C" void kernel_launch(void* const* d_in, const int* in_sizes, int n_in,
                              void* d_out, int out_size)
{
    const float* Cls = (const float*)d_in[0];
    const float* Shp = (const float*)d_in[1];
    const float* Off = (const float*)d_in[2];
    float* out = (float*)d_out;

    dim3 grid(S_SLICES, Bn);
    detfused<<<grid, NT>>>(Cls, Shp, Off, out);
}

// round 8
// speedup vs baseline: 2.0664x; 1.2429x over previous
#include <cuda_runtime.h>

#define Bn 64
#define Dd 32
#define Hh 48
#define Ww 48
#define NA (Dd*Hh*Ww)        /* 73728 anchors per batch */
#define TOPK 60
#define NMS_TOPK 20
#define THRESH 0.15f
#define NMS_T 0.05f
#define NBINS 4096
#define NT 1024
#define F4T (NA/4/NT)        /* 18 float4 per thread */
#define CHUNK 6              /* 3 chunks x 6 float4 */
#define CAND_FB 2304
#define T_RAW 2.9f

__device__ __forceinline__ unsigned fkey(float f) {
    unsigned u = __float_as_uint(f);
    return u ^ ((u & 0x80000000u) ? 0xFFFFFFFFu : 0x80000000u);
}
__device__ __forceinline__ float finv(unsigned k) {
    unsigned u = (k & 0x80000000u) ? (k ^ 0x80000000u) : ~k;
    return __uint_as_float(u);
}

__global__ __launch_bounds__(NT, 1)
void detone(const float* __restrict__ Cls,
            const float* __restrict__ Shp,
            const float* __restrict__ Off,
            float* __restrict__ out)
{
    const int b   = blockIdx.x;
    const int tid = threadIdx.x;

    __shared__ int s_cnt;
    __shared__ union UU {
        unsigned hist[NBINS];                 /* 16 KB, fallback only */
        unsigned long long cand[CAND_FB];     /* 18.4 KB */
    } u;
    __shared__ int partial[NT];
    __shared__ int thr_bin;
    __shared__ int cand_cnt;
    __shared__ float s_score[TOPK];
    __shared__ float s_ctr[TOPK][3];
    __shared__ float s_ext[TOPK][3];
    __shared__ unsigned char s_valid[TOPK];
    __shared__ unsigned long long s_mask[TOPK];
    __shared__ unsigned long long s_keep;

    const float4* c4 = (const float4*)(Cls + (size_t)b * NA);
    float* ob = out + (size_t)b * TOPK * 8;

    if (tid == 0) s_cnt = 0;
    if (tid < TOPK) s_mask[tid] = 0ull;
    // prefill output with -1 early (overwritten at the end by kept rows)
    if (tid < TOPK * 8) ob[tid] = -1.0f;
    __syncthreads();

    // ================= phase 1: one branchless pass, compact into smem ===========
    #pragma unroll
    for (int ch = 0; ch < F4T / CHUNK; ch++) {           // 3 chunks
        float4 q[CHUNK];
        const int cb = ch * CHUNK;
        #pragma unroll
        for (int j = 0; j < CHUNK; j++) q[j] = c4[(cb + j) * NT + tid];

        unsigned hm = 0;
        #pragma unroll
        for (int j = 0; j < CHUNK; j++) {
            float mx = fmaxf(fmaxf(q[j].x, q[j].y), fmaxf(q[j].z, q[j].w));
            hm |= (mx > T_RAW) ? (1u << j) : 0u;
        }
        if (hm) {                                        // rare (~2% of threads/chunk)
            #pragma unroll
            for (int j = 0; j < CHUNK; j++) {
                if (hm & (1u << j)) {
                    int gi = (cb + j) * NT + tid;
                    #pragma unroll
                    for (int k = 0; k < 4; k++) {
                        float f = (k == 0) ? q[j].x : (k == 1) ? q[j].y
                                : (k == 2) ? q[j].z : q[j].w;
                        if (f > T_RAW) {
                            int off = atomicAdd(&s_cnt, 1);
                            if (off < CAND_FB) {
                                unsigned idx = (unsigned)(gi * 4 + k);
                                u.cand[off] =
                                    ((unsigned long long)fkey(f) << 32) | (unsigned)(~idx);
                            }
                        }
                    }
                }
            }
        }
    }
    __syncthreads();

    int c = s_cnt;
    const bool fast = (c >= TOPK) && (c <= NT) && (c <= CAND_FB);

    if (fast) {
        // ---------- FAST PATH: rank-select top-60, gather boxes ----------
        bool act = (tid < c);
        unsigned long long k0 = act ? u.cand[tid] : 0ull;

        // issue scattered box loads NOW; overlap with the rank loop
        float az = 0, ay = 0, ax = 0;
        float o0 = 0, o1 = 0, o2 = 0, h0 = 0, h1 = 0, h2 = 0;
        if (act) {
            unsigned idx = ~(unsigned)(k0 & 0xFFFFFFFFull);
            int z = (int)idx / (Hh * Ww);
            int rem = (int)idx % (Hh * Ww);
            az = (float)z; ay = (float)(rem / Ww); ax = (float)(rem % Ww);
            size_t base3 = (size_t)b * 3 * NA + idx;
            o0 = Off[base3]; o1 = Off[base3 + NA]; o2 = Off[base3 + 2 * NA];
            h0 = Shp[base3]; h1 = Shp[base3 + NA]; h2 = Shp[base3 + 2 * NA];
        }

        int r0 = 0;
        for (int j = 0; j < c; j++)                      // broadcast LDS
            r0 += (u.cand[j] > k0) ? 1 : 0;

        if (act && r0 < TOPK) {
            float raw = finv((unsigned)(k0 >> 32));
            float sc  = 1.0f / (1.0f + __expf(-raw));
            s_score[r0] = sc;
            s_valid[r0] = (sc > THRESH) ? 1 : 0;
            s_ctr[r0][0] = (az + o0) * 2.0f;             // stride = (2,2,2)
            s_ctr[r0][1] = (ay + o1) * 2.0f;
            s_ctr[r0][2] = (ax + o2) * 2.0f;
            s_ext[r0][0] = 2.0f * h0;
            s_ext[r0][1] = 2.0f * h1;
            s_ext[r0][2] = 2.0f * h2;
        }
        __syncthreads();
    } else {
        // -------- exact histogram fallback (never hit on this data) --------
        const int lane = tid & 31;
        for (int i = tid; i < NBINS; i += NT) u.hist[i] = 0u;
        if (tid == 0) { thr_bin = 0; cand_cnt = 0; }
        __syncthreads();
        for (int i = tid; i < NA / 4; i += NT) {
            float4 v = c4[i];
            #pragma unroll
            for (int k = 0; k < 4; k++) {
                float f = (k == 0) ? v.x : (k == 1) ? v.y : (k == 2) ? v.z : v.w;
                int bin = (int)(fkey(f) >> 20);
                unsigned m = __match_any_sync(0xFFFFFFFFu, bin);
                if (lane == (__ffs(m) - 1))
                    atomicAdd(&u.hist[bin], (unsigned)__popc(m));
            }
        }
        __syncthreads();
        const int BPT = NBINS / NT;                      // 4
        int hbase = tid * BPT;
        int loc = 0;
        #pragma unroll
        for (int j = 0; j < BPT; j++) loc += (int)u.hist[hbase + j];
        partial[tid] = loc;
        __syncthreads();
        if (tid == 0) {
            int run = 0;
            for (int t = NT - 1; t >= 0; t--) { int p = partial[t]; partial[t] = run; run += p; }
        }
        __syncthreads();
        {
            int cum_above = partial[tid];
            if (cum_above < TOPK && cum_above + loc >= TOPK) {
                int cum = cum_above;
                for (int j = BPT - 1; j >= 0; j--) {
                    cum += (int)u.hist[hbase + j];
                    if (cum >= TOPK) { thr_bin = hbase + j; break; }
                }
            }
        }
        __syncthreads();
        const unsigned klow = (unsigned)thr_bin << 20;
        __syncthreads();                                 // done with hist before reuse
        for (int i = tid; i < NA / 4; i += NT) {
            float4 v = c4[i];
            #pragma unroll
            for (int k = 0; k < 4; k++) {
                float f = (k == 0) ? v.x : (k == 1) ? v.y : (k == 2) ? v.z : v.w;
                unsigned key = fkey(f);
                if (key >= klow) {
                    int pos = atomicAdd(&cand_cnt, 1);
                    if (pos < CAND_FB) {
                        unsigned idx = (unsigned)(i * 4 + k);
                        u.cand[pos] = ((unsigned long long)key << 32) | (unsigned)(~idx);
                    }
                }
            }
        }
        __syncthreads();

        const int cf = min(cand_cnt, CAND_FB);
        for (int i = tid; i < cf; i += NT) {
            unsigned long long ki = u.cand[i];
            int rank = 0;
            for (int j = 0; j < cf; j++) rank += (u.cand[j] > ki) ? 1 : 0;
            if (rank < TOPK) {
                unsigned key = (unsigned)(ki >> 32);
                unsigned idx = ~(unsigned)(ki & 0xFFFFFFFFull);
                float raw = finv(key);
                float sc  = 1.0f / (1.0f + expf(-raw));
                s_score[rank] = sc;
                s_valid[rank] = (sc > THRESH) ? 1 : 0;
                int z   = (int)idx / (Hh * Ww);
                int rem = (int)idx % (Hh * Ww);
                int y   = rem / Ww;
                int x   = rem % Ww;
                size_t base3 = (size_t)b * 3 * NA + idx;
                float o0 = Off[base3], o1 = Off[base3 + NA], o2 = Off[base3 + 2 * NA];
                float h0 = Shp[base3], h1 = Shp[base3 + NA], h2 = Shp[base3 + 2 * NA];
                s_ctr[rank][0] = ((float)z + o0) * 2.0f;
                s_ctr[rank][1] = ((float)y + o1) * 2.0f;
                s_ctr[rank][2] = ((float)x + o2) * 2.0f;
                s_ext[rank][0] = 2.0f * h0;
                s_ext[rank][1] = 2.0f * h1;
                s_ext[rank][2] = 2.0f * h2;
            }
        }
        __syncthreads();
    }

    // ---- IoU > NMS_T bitmask: 17 strips x 4 cols per row ----
    {
        int i = tid % TOPK;           // row
        int q = tid / TOPK;           // strip (tid < 1020 -> q < 17)
        if (q < 17) {
            float ci0 = s_ctr[i][0], ci1 = s_ctr[i][1], ci2 = s_ctr[i][2];
            float ei0 = s_ext[i][0], ei1 = s_ext[i][1], ei2 = s_ext[i][2];
            float li0 = ci0 - 0.5f * ei0, li1 = ci1 - 0.5f * ei1, li2 = ci2 - 0.5f * ei2;
            float hi0 = ci0 + 0.5f * ei0, hi1 = ci1 + 0.5f * ei1, hi2 = ci2 + 0.5f * ei2;
            float vi  = ei0 * ei1 * ei2;
            unsigned long long m = 0ull;
            int j0 = q * 4;
            #pragma unroll
            for (int t = 0; t < 4; t++) {
                int j = j0 + t;
                if (j < TOPK) {
                    float ej0 = s_ext[j][0], ej1 = s_ext[j][1], ej2 = s_ext[j][2];
                    float lj0 = s_ctr[j][0] - 0.5f * ej0;
                    float lj1 = s_ctr[j][1] - 0.5f * ej1;
                    float lj2 = s_ctr[j][2] - 0.5f * ej2;
                    float hj0 = s_ctr[j][0] + 0.5f * ej0;
                    float hj1 = s_ctr[j][1] + 0.5f * ej1;
                    float hj2 = s_ctr[j][2] + 0.5f * ej2;
                    float d0 = fminf(hi0, hj0) - fmaxf(li0, lj0);
                    float d1 = fminf(hi1, hj1) - fmaxf(li1, lj1);
                    float d2 = fminf(hi2, hj2) - fmaxf(li2, lj2);
                    float inter = fmaxf(d0, 0.0f) * fmaxf(d1, 0.0f) * fmaxf(d2, 0.0f);
                    float vj  = ej0 * ej1 * ej2;
                    float un  = vi + vj - inter;
                    float iou = inter / fmaxf(un, 1e-8f);
                    if (iou > NMS_T) m |= (1ull << j);
                }
            }
            if (m) atomicOr(&s_mask[i], m);
        }
    }
    __syncthreads();

    // ---- greedy NMS on a u64 mask ----
    if (tid == 0) {
        unsigned long long km = 0ull;
        #pragma unroll 4
        for (int i = 0; i < TOPK; i++)
            if (s_valid[i] && !(s_mask[i] & km)) km |= (1ull << i);
        s_keep = km;
    }
    __syncthreads();

    // ---- write kept rows at their rank (output already -1-filled) ----
    if (tid < TOPK) {
        unsigned long long km = s_keep;
        if ((km >> tid) & 1ull) {
            int rank = __popcll(km & ((1ull << tid) - 1ull));
            if (rank < NMS_TOPK) {
                float* row = ob + (size_t)rank * 8;
                row[0] = 1.0f;
                row[1] = s_score[tid];
                row[2] = s_ctr[tid][0];
                row[3] = s_ctr[tid][1];
                row[4] = s_ctr[tid][2];
                row[5] = s_ext[tid][0];
                row[6] = s_ext[tid][1];
                row[7] = s_ext[tid][2];
            }
        }
    }
}

extern "C" void kernel_launch(void* const* d_in, const int* in_sizes, int n_in,
                              void* d_out, int out_size)
{
    const float* Cls = (const float*)d_in[0];
    const float* Shp = (const float*)d_in[1];
    const float* Off = (const float*)d_in[2];
    float* out = (float*)d_out;

    detone<<<Bn, NT>>>(Cls, Shp, Off, out);
}